// round 7
// baseline (speedup 1.0000x reference)
#include <cuda_runtime.h>
#include <cuda_fp16.h>
#include <mma.h>
#include <math.h>
#include <cstdint>

using namespace nvcuda;

#define NTOK 4096
#define DDIM 1024
#define HDIM 4096
#define ODIM 1024
#define NEXP 8
#define NPAIR 8192

#define BM 128
#define BN 128
#define BK 32
#define ALD 40      // A smem row stride (halfs)
#define BLD 136     // B smem row stride (halfs)
#define CLD 132     // C smem row stride (floats)

#define A_STAGE 10240              // 128*40*2
#define B_STAGE 8704               // 32*136*2 (per term)
#define STG (A_STAGE + 2 * B_STAGE)   // 27648
#define OFF_BH A_STAGE
#define OFF_BL (A_STAGE + B_STAGE)
#define NSTAGE 4
#define SMEM_GEMM (NSTAGE * STG)   // 110592; C tile 128*132*4=67584 aliases
#define RLD 1028                   // router smem row stride (floats)
#define SMEM_ROUTER (16 * RLD * 4) // 65792

__device__ __forceinline__ uint32_t smem_u32(const void* p) {
    uint32_t a;
    asm("{ .reg .u64 t; cvta.to.shared.u64 t, %1; cvt.u32.u64 %0, t; }" : "=r"(a) : "l"(p));
    return a;
}
#define CP_ASYNC16(dst, src, sz) \
    asm volatile("cp.async.cg.shared.global [%0], [%1], 16, %2;" \
                 :: "r"(dst), "l"(src), "r"(sz))
#define CP_COMMIT() asm volatile("cp.async.commit_group;")
#define CP_WAIT0()  asm volatile("cp.async.wait_group 0;")
#define CP_WAIT1()  asm volatile("cp.async.wait_group 1;")
#define CP_WAIT2()  asm volatile("cp.async.wait_group 2;")

// ---------------- scratch (device globals) ----------------
__device__ int   g_cnt[NEXP];
__device__ int   g_tok[NEXP * NTOK];
__device__ float g_gate[NEXP * NTOK];
__device__ __half g_xh[NTOK * DDIM];                 // fp16(x)
__device__ __half g_w1h[NEXP * DDIM * HDIM];         // fp16 hi
__device__ __half g_w1l[NEXP * DDIM * HDIM];         // fp16 lo (residual)
__device__ __half g_w2h[NEXP * HDIM * ODIM];
__device__ __half g_w2l[NEXP * HDIM * ODIM];
__device__ __half g_h[(size_t)NPAIR * HDIM];         // fp16(h)

// ---------------- x: fp32 -> fp16 convert ----------------
__global__ void conv_x_kernel(const float4* __restrict__ src) {
    int i = blockIdx.x * blockDim.x + threadIdx.x;
    if (i >= NTOK * DDIM / 4) return;
    float4 v = src[i];
    __half2* dst = (__half2*)g_xh;
    dst[2 * i]     = __halves2half2(__float2half_rn(v.x), __float2half_rn(v.y));
    dst[2 * i + 1] = __halves2half2(__float2half_rn(v.z), __float2half_rn(v.w));
}

// ---------------- W1 + W2: fp32 -> fp16 hi/lo split ----------------
__global__ void split_w_kernel(const float4* __restrict__ W1,
                               const float4* __restrict__ W2) {
    const int n4 = NEXP * DDIM * HDIM / 4;
    int i = blockIdx.x * blockDim.x + threadIdx.x;
    if (i >= 2 * n4) return;
    bool second = i >= n4;
    int j = second ? i - n4 : i;
    float4 v = second ? W2[j] : W1[j];
    __half h0 = __float2half_rn(v.x);
    __half h1 = __float2half_rn(v.y);
    __half h2 = __float2half_rn(v.z);
    __half h3 = __float2half_rn(v.w);
    __half2* hi = (__half2*)(second ? g_w2h : g_w1h);
    __half2* lo = (__half2*)(second ? g_w2l : g_w1l);
    hi[2 * j]     = __halves2half2(h0, h1);
    hi[2 * j + 1] = __halves2half2(h2, h3);
    lo[2 * j]     = __halves2half2(__float2half_rn(v.x - __half2float(h0)),
                                   __float2half_rn(v.y - __half2float(h1)));
    lo[2 * j + 1] = __halves2half2(__float2half_rn(v.z - __half2float(h2)),
                                   __float2half_rn(v.w - __half2float(h3)));
}

// ---------------- router: expert-per-lane, 2 tokens/warp ----------------
__global__ void router_kernel(const float* __restrict__ x,
                              const float* __restrict__ noise,
                              const float* __restrict__ Wg,
                              const float* __restrict__ bg,
                              const float* __restrict__ Wn,
                              const float* __restrict__ bn) {
    extern __shared__ float Ws[];  // [16][RLD] rows: 0..7 Wg cols, 8..15 Wn cols
    int tid = threadIdx.x;
    for (int idx = tid; idx < DDIM * NEXP; idx += blockDim.x) {
        int k = idx >> 3, o = idx & 7;
        Ws[o * RLD + k]       = Wg[idx];
        Ws[(8 + o) * RLD + k] = Wn[idx];
    }
    __syncthreads();
    int warp = tid >> 5, lane = tid & 31;
    int o = lane & 15, half = lane >> 4;
    int t = blockIdx.x * 16 + warp * 2 + half;

    const float4* xr = (const float4*)(x + (size_t)t * DDIM);
    const float4* wr = (const float4*)(Ws + o * RLD);
    float acc = 0.f;
#pragma unroll 8
    for (int k = 0; k < 256; ++k) {
        float4 xv = xr[k];
        float4 wv = wr[k];
        acc += xv.x * wv.x + xv.y * wv.y + xv.z * wv.z + xv.w * wv.w;
    }
    float nl_other = __shfl_sync(0xffffffffu, acc, (lane + 8) & 31);
    float noisy = -3.4e38f;
    if (o < 8) {
        float lg = acc + bg[o];
        float nl = nl_other + bn[o];
        float sp = nl > 20.f ? nl : log1pf(expf(nl));
        noisy = lg + noise[(size_t)t * 8 + o] * sp;
    }
    float v[8];
#pragma unroll
    for (int oo = 0; oo < 8; ++oo)
        v[oo] = __shfl_sync(0xffffffffu, noisy, (half << 4) + oo);
    if (o == 0) {
        int i1 = 0; float v1 = v[0];
#pragma unroll
        for (int oo = 1; oo < 8; ++oo) if (v[oo] > v1) { v1 = v[oo]; i1 = oo; }
        int i2 = 0; float v2 = -3.4e38f;
#pragma unroll
        for (int oo = 0; oo < 8; ++oo) if (oo != i1 && v[oo] > v2) { v2 = v[oo]; i2 = oo; }
        float ex = expf(v2 - v1);
        float inv = 1.f / (1.f + ex);
        int p1 = atomicAdd(&g_cnt[i1], 1);
        g_tok[i1 * NTOK + p1]  = t;
        g_gate[i1 * NTOK + p1] = inv;
        int p2 = atomicAdd(&g_cnt[i2], 1);
        g_tok[i2 * NTOK + p2]  = t;
        g_gate[i2 * NTOK + p2] = ex * inv;
    }
}

// ---------------- grouped GEMM (fp16 2-term, 8 warps 64x32, 4-stage) ----------------
// SECOND=false: h = relu(gather(xh) @ (W1h+W1l)[e] + b1[e]) -> g_h (fp16)
// SECOND=true : out += gate * (h @ (W2h+W2l)[e] + b2[e])
template <bool SECOND>
__global__ void __launch_bounds__(256, 2)
moe_gemm_kernel(const float* __restrict__ bias, float* __restrict__ out) {
    constexpr int KDIM = SECOND ? HDIM : DDIM;
    constexpr int NDIM = SECOND ? ODIM : HDIM;
    constexpr int KT = KDIM / BK;

    int e  = blockIdx.y >> 5;
    int mt = blockIdx.y & 31;
    int cnt = g_cnt[e];
    int m0 = mt * BM;
    if (m0 >= cnt) return;
    int off = 0;
#pragma unroll
    for (int q = 0; q < NEXP; ++q) off += (q < e) ? g_cnt[q] : 0;
    int n0 = blockIdx.x * BN;
    int tid = threadIdx.x;
    int w = tid >> 5;
    int wm = (w & 1) * 64, wn = (w >> 1) * 32;

    extern __shared__ __align__(128) char raw[];
    uint32_t sbase = smem_u32(raw);

    const __half* Asrc = SECOND ? g_h : g_xh;
    const __half* Bhi  = SECOND ? g_w2h : g_w1h;
    const __half* Blo  = SECOND ? g_w2l : g_w1l;

    // A: chunk id = tid + 256*i (i<2): row = id>>2, c = id&3 (8 halfs = 16B)
    size_t asrc[2]; uint32_t asz[2]; uint32_t adst[2];
#pragma unroll
    for (int i = 0; i < 2; ++i) {
        int id = tid + 256 * i;
        int row = id >> 2, c = id & 3;
        int pos = m0 + row;
        bool aval = pos < cnt;
        asz[i] = aval ? 16u : 0u;
        if (SECOND) {
            asrc[i] = (size_t)(off + (aval ? pos : 0)) * HDIM + c * 8;
        } else {
            int token = aval ? g_tok[e * NTOK + pos] : 0;
            asrc[i] = (size_t)token * DDIM + c * 8;
        }
        adst[i] = sbase + row * (ALD * 2) + c * 16;
    }
    // B: chunk id = tid + 256*i (i<2): row = id>>4, c16 = id&15
    size_t bsrc[2]; uint32_t bdst[2];
#pragma unroll
    for (int i = 0; i < 2; ++i) {
        int id = tid + 256 * i;
        int row = id >> 4, c16 = id & 15;
        bsrc[i] = (size_t)e * KDIM * NDIM + (size_t)row * NDIM + n0 + c16 * 8;
        bdst[i] = sbase + OFF_BH + row * (BLD * 2) + c16 * 16;
    }

    auto fill = [&](int s, int kt) {
        int ko = kt * BK;
        uint32_t sb = s * STG;
#pragma unroll
        for (int i = 0; i < 2; ++i)
            CP_ASYNC16(adst[i] + sb, (const char*)(Asrc + asrc[i] + ko), asz[i]);
        size_t kofs = (size_t)ko * NDIM;
#pragma unroll
        for (int i = 0; i < 2; ++i) {
            CP_ASYNC16(bdst[i] + sb, (const char*)(Bhi + bsrc[i] + kofs), 16u);
            CP_ASYNC16(bdst[i] + sb + B_STAGE, (const char*)(Blo + bsrc[i] + kofs), 16u);
        }
        CP_COMMIT();
    };

    wmma::fragment<wmma::accumulator, 16, 16, 16, float> acc[4][2];
#pragma unroll
    for (int i = 0; i < 4; ++i)
#pragma unroll
        for (int j = 0; j < 2; ++j) wmma::fill_fragment(acc[i][j], 0.f);

    auto compute = [&](int s) {
        const __half* Ah = (const __half*)(raw + s * STG);
        const __half* Bh = (const __half*)(raw + s * STG + OFF_BH);
        const __half* Bl = (const __half*)(raw + s * STG + OFF_BL);
#pragma unroll
        for (int kk = 0; kk < BK; kk += 16) {
            wmma::fragment<wmma::matrix_a, 16, 16, 16, __half, wmma::row_major> fa[4];
#pragma unroll
            for (int i = 0; i < 4; ++i)
                wmma::load_matrix_sync(fa[i], Ah + (wm + 16 * i) * ALD + kk, ALD);
#pragma unroll
            for (int j = 0; j < 2; ++j) {
                wmma::fragment<wmma::matrix_b, 16, 16, 16, __half, wmma::row_major> fb;
                wmma::load_matrix_sync(fb, Bh + kk * BLD + wn + 16 * j, BLD);
#pragma unroll
                for (int i = 0; i < 4; ++i)
                    wmma::mma_sync(acc[i][j], fa[i], fb, acc[i][j]);
                wmma::load_matrix_sync(fb, Bl + kk * BLD + wn + 16 * j, BLD);
#pragma unroll
                for (int i = 0; i < 4; ++i)
                    wmma::mma_sync(acc[i][j], fa[i], fb, acc[i][j]);
            }
        }
    };

    fill(0, 0);
    fill(1, 1);
    fill(2, 2);
#pragma unroll 1
    for (int kt = 0; kt < KT; ++kt) {
        int rem = KT - kt;
        if (rem >= 3) CP_WAIT2();
        else if (rem == 2) CP_WAIT1();
        else CP_WAIT0();
        __syncthreads();
        if (kt + 3 < KT) fill((kt + 3) & 3, kt + 3);
        compute(kt & 3);
    }

    // epilogue via smem C tile (aliased over stage buffers)
    __syncthreads();
    float* sC = (float*)raw;
#pragma unroll
    for (int i = 0; i < 4; ++i)
#pragma unroll
        for (int j = 0; j < 2; ++j)
            wmma::store_matrix_sync(sC + (wm + 16 * i) * CLD + wn + 16 * j, acc[i][j], CLD,
                                    wmma::mem_row_major);
    __syncthreads();

    if (!SECOND) {
        for (int q = tid; q < BM * (BN / 8); q += 256) {
            int r = q >> 4;
            int c = (q & 15) * 8;
            int pos = m0 + r;
            if (pos >= cnt) continue;
            int nb = n0 + c;
            uint4 pk;
            __half2 p[4];
#pragma unroll
            for (int u = 0; u < 4; ++u) {
                float v0 = sC[r * CLD + c + 2 * u]     + bias[e * NDIM + nb + 2 * u];
                float v1 = sC[r * CLD + c + 2 * u + 1] + bias[e * NDIM + nb + 2 * u + 1];
                p[u] = __halves2half2(__float2half_rn(fmaxf(v0, 0.f)),
                                      __float2half_rn(fmaxf(v1, 0.f)));
            }
            pk.x = *(uint32_t*)&p[0]; pk.y = *(uint32_t*)&p[1];
            pk.z = *(uint32_t*)&p[2]; pk.w = *(uint32_t*)&p[3];
            *(uint4*)(g_h + (size_t)(off + pos) * HDIM + nb) = pk;
        }
    } else {
        for (int q = tid; q < BM * (BN / 4); q += 256) {
            int r = q >> 5;
            int c = (q & 31) * 4;
            int pos = m0 + r;
            if (pos >= cnt) continue;
            float gate = g_gate[e * NTOK + pos];
            int token  = g_tok[e * NTOK + pos];
            int nb = n0 + c;
            float* op = out + (size_t)token * ODIM + nb;
#pragma unroll
            for (int u = 0; u < 4; ++u) {
                float v = sC[r * CLD + c + u] + bias[e * NDIM + nb + u];
                atomicAdd(op + u, v * gate);
            }
        }
    }
}

// ---------------- launch ----------------
extern "C" void kernel_launch(void* const* d_in, const int* in_sizes, int n_in,
                              void* d_out, int out_size) {
    const float* x     = (const float*)d_in[0];
    const float* noise = (const float*)d_in[1];
    const float* Wg    = (const float*)d_in[2];
    const float* bg    = (const float*)d_in[3];
    const float* Wn    = (const float*)d_in[4];
    const float* bn    = (const float*)d_in[5];
    const float* W1    = (const float*)d_in[6];
    const float* b1    = (const float*)d_in[7];
    const float* W2    = (const float*)d_in[8];
    const float* b2    = (const float*)d_in[9];
    (void)in_sizes; (void)n_in;

    void* cnt_ptr;
    cudaGetSymbolAddress(&cnt_ptr, g_cnt);

    cudaFuncSetAttribute(router_kernel, cudaFuncAttributeMaxDynamicSharedMemorySize, SMEM_ROUTER);
    cudaFuncSetAttribute(moe_gemm_kernel<false>, cudaFuncAttributeMaxDynamicSharedMemorySize, SMEM_GEMM);
    cudaFuncSetAttribute(moe_gemm_kernel<true>,  cudaFuncAttributeMaxDynamicSharedMemorySize, SMEM_GEMM);

    // launch order: gemm1 is profiled launch index 5 (ncu -s 5 -c 1)
    cudaMemsetAsync(cnt_ptr, 0, NEXP * sizeof(int));                       // 0
    cudaMemsetAsync(d_out, 0, (size_t)out_size * sizeof(float));           // 1

    int n4x = NTOK * DDIM / 4;
    conv_x_kernel<<<(n4x + 255) / 256, 256>>>((const float4*)x);           // 2
    int n4w = NEXP * DDIM * HDIM / 4;
    split_w_kernel<<<(2 * n4w + 255) / 256, 256>>>((const float4*)W1,
                                                   (const float4*)W2);     // 3
    router_kernel<<<NTOK / 16, 256, SMEM_ROUTER>>>(x, noise, Wg, bg, Wn, bn); // 4

    moe_gemm_kernel<false><<<dim3(HDIM / BN, NEXP * 32), 256, SMEM_GEMM>>>(b1, nullptr);      // 5
    moe_gemm_kernel<true> <<<dim3(ODIM / BN, NEXP * 32), 256, SMEM_GEMM>>>(b2, (float*)d_out); // 6
}

// round 8
// speedup vs baseline: 1.4447x; 1.4447x over previous
#include <cuda_runtime.h>
#include <cuda_fp16.h>
#include <mma.h>
#include <math.h>
#include <cstdint>

using namespace nvcuda;

#define NTOK 4096
#define DDIM 1024
#define HDIM 4096
#define ODIM 1024
#define NEXP 8
#define NPAIR 8192

#define BM 128
#define BN 256
#define BK 64
#define ALD 72      // A smem row stride (halfs)
#define BLD 264     // B smem row stride (halfs)
#define CLD 264     // C smem row stride (floats)

#define A_STAGE 18432             // 128*72*2
#define B_STAGE 33792             // 64*264*2
#define STG (A_STAGE + B_STAGE)   // 52224
#define OFF_B A_STAGE
#define NSTAGE 3
#define SMEM_GEMM (NSTAGE * STG)  // 156672 (C tile 128*264*4=135168 aliases)
#define RLD 1028                  // router smem row stride (floats)
#define SMEM_ROUTER (16 * RLD * 4)

__device__ __forceinline__ uint32_t smem_u32(const void* p) {
    uint32_t a;
    asm("{ .reg .u64 t; cvta.to.shared.u64 t, %1; cvt.u32.u64 %0, t; }" : "=r"(a) : "l"(p));
    return a;
}
#define CP_ASYNC16(dst, src, sz) \
    asm volatile("cp.async.cg.shared.global [%0], [%1], 16, %2;" \
                 :: "r"(dst), "l"(src), "r"(sz))
#define CP_COMMIT() asm volatile("cp.async.commit_group;")
#define CP_WAIT0()  asm volatile("cp.async.wait_group 0;")
#define CP_WAIT1()  asm volatile("cp.async.wait_group 1;")

// ---------------- scratch (device globals) ----------------
__device__ int   g_cnt[NEXP];
__device__ int   g_tok[NEXP * NTOK];
__device__ float g_gate[NEXP * NTOK];
__device__ __half g_xh[NTOK * DDIM];                 // fp16(x)
__device__ __half g_w1h[NEXP * DDIM * HDIM];         // fp16(W1)
__device__ __half g_w2h[NEXP * HDIM * ODIM];         // fp16(W2)
__device__ __half g_h[(size_t)NPAIR * HDIM];         // fp16(h)

// ---------------- x: fp32 -> fp16 ----------------
__global__ void conv_x_kernel(const float4* __restrict__ src) {
    int i = blockIdx.x * blockDim.x + threadIdx.x;
    if (i >= NTOK * DDIM / 4) return;
    float4 v = src[i];
    __half2* dst = (__half2*)g_xh;
    dst[2 * i]     = __halves2half2(__float2half_rn(v.x), __float2half_rn(v.y));
    dst[2 * i + 1] = __halves2half2(__float2half_rn(v.z), __float2half_rn(v.w));
}

// ---------------- W1 + W2: fp32 -> fp16 ----------------
__global__ void conv_w_kernel(const float4* __restrict__ W1,
                              const float4* __restrict__ W2) {
    const int n4 = NEXP * DDIM * HDIM / 4;
    int i = blockIdx.x * blockDim.x + threadIdx.x;
    if (i >= 2 * n4) return;
    bool second = i >= n4;
    int j = second ? i - n4 : i;
    float4 v = second ? W2[j] : W1[j];
    __half2* hi = (__half2*)(second ? g_w2h : g_w1h);
    hi[2 * j]     = __halves2half2(__float2half_rn(v.x), __float2half_rn(v.y));
    hi[2 * j + 1] = __halves2half2(__float2half_rn(v.z), __float2half_rn(v.w));
}

// ---------------- router: expert-per-lane, 2 tokens/warp ----------------
__global__ void router_kernel(const float* __restrict__ x,
                              const float* __restrict__ noise,
                              const float* __restrict__ Wg,
                              const float* __restrict__ bg,
                              const float* __restrict__ Wn,
                              const float* __restrict__ bn) {
    extern __shared__ float Ws[];  // [16][RLD] rows: 0..7 Wg cols, 8..15 Wn cols
    int tid = threadIdx.x;
    for (int idx = tid; idx < DDIM * NEXP; idx += blockDim.x) {
        int k = idx >> 3, o = idx & 7;
        Ws[o * RLD + k]       = Wg[idx];
        Ws[(8 + o) * RLD + k] = Wn[idx];
    }
    __syncthreads();
    int warp = tid >> 5, lane = tid & 31;
    int o = lane & 15, half = lane >> 4;
    int t = blockIdx.x * 16 + warp * 2 + half;

    const float4* xr = (const float4*)(x + (size_t)t * DDIM);
    const float4* wr = (const float4*)(Ws + o * RLD);
    float acc = 0.f;
#pragma unroll 8
    for (int k = 0; k < 256; ++k) {
        float4 xv = xr[k];
        float4 wv = wr[k];
        acc += xv.x * wv.x + xv.y * wv.y + xv.z * wv.z + xv.w * wv.w;
    }
    float nl_other = __shfl_sync(0xffffffffu, acc, (lane + 8) & 31);
    float noisy = -3.4e38f;
    if (o < 8) {
        float lg = acc + bg[o];
        float nl = nl_other + bn[o];
        float sp = nl > 20.f ? nl : log1pf(expf(nl));
        noisy = lg + noise[(size_t)t * 8 + o] * sp;
    }
    float v[8];
#pragma unroll
    for (int oo = 0; oo < 8; ++oo)
        v[oo] = __shfl_sync(0xffffffffu, noisy, (half << 4) + oo);
    if (o == 0) {
        int i1 = 0; float v1 = v[0];
#pragma unroll
        for (int oo = 1; oo < 8; ++oo) if (v[oo] > v1) { v1 = v[oo]; i1 = oo; }
        int i2 = 0; float v2 = -3.4e38f;
#pragma unroll
        for (int oo = 0; oo < 8; ++oo) if (oo != i1 && v[oo] > v2) { v2 = v[oo]; i2 = oo; }
        float ex = expf(v2 - v1);
        float inv = 1.f / (1.f + ex);
        int p1 = atomicAdd(&g_cnt[i1], 1);
        g_tok[i1 * NTOK + p1]  = t;
        g_gate[i1 * NTOK + p1] = inv;
        int p2 = atomicAdd(&g_cnt[i2], 1);
        g_tok[i2 * NTOK + p2]  = t;
        g_gate[i2 * NTOK + p2] = ex * inv;
    }
}

// ---------------- grouped GEMM (single fp16, 8 warps 64x64, 3-stage) ----------------
// SECOND=false: h = relu(gather(xh) @ W1h[e] + b1[e]) -> g_h (fp16)
// SECOND=true : out += gate * (h @ W2h[e] + b2[e])
template <bool SECOND>
__global__ void __launch_bounds__(256, 1)
moe_gemm_kernel(const float* __restrict__ bias, float* __restrict__ out) {
    constexpr int KDIM = SECOND ? HDIM : DDIM;
    constexpr int NDIM = SECOND ? ODIM : HDIM;
    constexpr int KT = KDIM / BK;

    int e  = blockIdx.y >> 5;
    int mt = blockIdx.y & 31;
    int cnt = g_cnt[e];
    int m0 = mt * BM;
    if (m0 >= cnt) return;
    int off = 0;
#pragma unroll
    for (int q = 0; q < NEXP; ++q) off += (q < e) ? g_cnt[q] : 0;
    int n0 = blockIdx.x * BN;
    int tid = threadIdx.x;
    int w = tid >> 5;
    int wm = (w & 1) * 64, wn = (w >> 1) * 64;

    extern __shared__ __align__(128) char raw[];
    uint32_t sbase = smem_u32(raw);

    const __half* Asrc = SECOND ? g_h : g_xh;
    const __half* Bsrc = SECOND ? g_w2h : g_w1h;

    // A: chunk id = tid + 256*i (i<4): row = id>>3, c8 = id&7 (8 halfs = 16B)
    size_t asrc[4]; uint32_t asz[4]; uint32_t adst[4];
#pragma unroll
    for (int i = 0; i < 4; ++i) {
        int id = tid + 256 * i;
        int row = id >> 3, c8 = id & 7;
        int pos = m0 + row;
        bool aval = pos < cnt;
        asz[i] = aval ? 16u : 0u;
        if (SECOND) {
            asrc[i] = (size_t)(off + (aval ? pos : 0)) * HDIM + c8 * 8;
        } else {
            int token = aval ? g_tok[e * NTOK + pos] : 0;
            asrc[i] = (size_t)token * DDIM + c8 * 8;
        }
        adst[i] = sbase + row * (ALD * 2) + c8 * 16;
    }
    // B: chunk id = tid + 256*i (i<8): row = id>>5, c16 = id&31
    size_t bsrc[8]; uint32_t bdst[8];
#pragma unroll
    for (int i = 0; i < 8; ++i) {
        int id = tid + 256 * i;
        int row = id >> 5, c16 = id & 31;
        bsrc[i] = (size_t)e * KDIM * NDIM + (size_t)row * NDIM + n0 + c16 * 8;
        bdst[i] = sbase + OFF_B + row * (BLD * 2) + c16 * 16;
    }

    auto fill = [&](int s, int kt) {
        int ko = kt * BK;
        uint32_t sb = s * STG;
#pragma unroll
        for (int i = 0; i < 4; ++i)
            CP_ASYNC16(adst[i] + sb, (const char*)(Asrc + asrc[i] + ko), asz[i]);
        size_t kofs = (size_t)ko * NDIM;
#pragma unroll
        for (int i = 0; i < 8; ++i)
            CP_ASYNC16(bdst[i] + sb, (const char*)(Bsrc + bsrc[i] + kofs), 16u);
        CP_COMMIT();
    };

    wmma::fragment<wmma::accumulator, 16, 16, 16, float> acc[4][4];
#pragma unroll
    for (int i = 0; i < 4; ++i)
#pragma unroll
        for (int j = 0; j < 4; ++j) wmma::fill_fragment(acc[i][j], 0.f);

    auto compute = [&](int s) {
        const __half* Ah = (const __half*)(raw + s * STG);
        const __half* Bh = (const __half*)(raw + s * STG + OFF_B);
#pragma unroll
        for (int kk = 0; kk < BK; kk += 16) {
            wmma::fragment<wmma::matrix_a, 16, 16, 16, __half, wmma::row_major> fa[4];
            wmma::fragment<wmma::matrix_b, 16, 16, 16, __half, wmma::row_major> fb[4];
#pragma unroll
            for (int i = 0; i < 4; ++i)
                wmma::load_matrix_sync(fa[i], Ah + (wm + 16 * i) * ALD + kk, ALD);
#pragma unroll
            for (int j = 0; j < 4; ++j)
                wmma::load_matrix_sync(fb[j], Bh + kk * BLD + wn + 16 * j, BLD);
#pragma unroll
            for (int i = 0; i < 4; ++i)
#pragma unroll
                for (int j = 0; j < 4; ++j)
                    wmma::mma_sync(acc[i][j], fa[i], fb[j], acc[i][j]);
        }
    };

    fill(0, 0);
    fill(1, 1);
#pragma unroll 1
    for (int kt = 0; kt < KT; ++kt) {
        if (KT - kt >= 2) CP_WAIT1(); else CP_WAIT0();
        __syncthreads();
        if (kt + 2 < KT) fill((kt + 2) % NSTAGE, kt + 2);
        compute(kt % NSTAGE);
    }

    // epilogue via smem C tile (aliased over stage buffers)
    __syncthreads();
    float* sC = (float*)raw;
#pragma unroll
    for (int i = 0; i < 4; ++i)
#pragma unroll
        for (int j = 0; j < 4; ++j)
            wmma::store_matrix_sync(sC + (wm + 16 * i) * CLD + wn + 16 * j, acc[i][j], CLD,
                                    wmma::mem_row_major);
    __syncthreads();

    if (!SECOND) {
        for (int q = tid; q < BM * (BN / 8); q += 256) {
            int r = q >> 5;
            int c = (q & 31) * 8;
            int pos = m0 + r;
            if (pos >= cnt) continue;
            int nb = n0 + c;
            uint4 pk;
            __half2 p[4];
#pragma unroll
            for (int u = 0; u < 4; ++u) {
                float v0 = sC[r * CLD + c + 2 * u]     + bias[e * NDIM + nb + 2 * u];
                float v1 = sC[r * CLD + c + 2 * u + 1] + bias[e * NDIM + nb + 2 * u + 1];
                p[u] = __halves2half2(__float2half_rn(fmaxf(v0, 0.f)),
                                      __float2half_rn(fmaxf(v1, 0.f)));
            }
            pk.x = *(uint32_t*)&p[0]; pk.y = *(uint32_t*)&p[1];
            pk.z = *(uint32_t*)&p[2]; pk.w = *(uint32_t*)&p[3];
            *(uint4*)(g_h + (size_t)(off + pos) * HDIM + nb) = pk;
        }
    } else {
        for (int q = tid; q < BM * (BN / 4); q += 256) {
            int r = q >> 6;
            int c = (q & 63) * 4;
            int pos = m0 + r;
            if (pos >= cnt) continue;
            float gate = g_gate[e * NTOK + pos];
            int token  = g_tok[e * NTOK + pos];
            int nb = n0 + c;
            float* op = out + (size_t)token * ODIM + nb;
#pragma unroll
            for (int u = 0; u < 4; ++u) {
                float v = sC[r * CLD + c + u] + bias[e * NDIM + nb + u];
                atomicAdd(op + u, v * gate);
            }
        }
    }
}

// ---------------- launch ----------------
extern "C" void kernel_launch(void* const* d_in, const int* in_sizes, int n_in,
                              void* d_out, int out_size) {
    const float* x     = (const float*)d_in[0];
    const float* noise = (const float*)d_in[1];
    const float* Wg    = (const float*)d_in[2];
    const float* bg    = (const float*)d_in[3];
    const float* Wn    = (const float*)d_in[4];
    const float* bn    = (const float*)d_in[5];
    const float* W1    = (const float*)d_in[6];
    const float* b1    = (const float*)d_in[7];
    const float* W2    = (const float*)d_in[8];
    const float* b2    = (const float*)d_in[9];
    (void)in_sizes; (void)n_in;

    void* cnt_ptr;
    cudaGetSymbolAddress(&cnt_ptr, g_cnt);

    cudaFuncSetAttribute(router_kernel, cudaFuncAttributeMaxDynamicSharedMemorySize, SMEM_ROUTER);
    cudaFuncSetAttribute(moe_gemm_kernel<false>, cudaFuncAttributeMaxDynamicSharedMemorySize, SMEM_GEMM);
    cudaFuncSetAttribute(moe_gemm_kernel<true>,  cudaFuncAttributeMaxDynamicSharedMemorySize, SMEM_GEMM);

    // launch order: gemm1 is profiled launch index 5 (ncu -s 5 -c 1)
    cudaMemsetAsync(cnt_ptr, 0, NEXP * sizeof(int));                       // 0
    cudaMemsetAsync(d_out, 0, (size_t)out_size * sizeof(float));           // 1

    int n4x = NTOK * DDIM / 4;
    conv_x_kernel<<<(n4x + 255) / 256, 256>>>((const float4*)x);           // 2
    int n4w = NEXP * DDIM * HDIM / 4;
    conv_w_kernel<<<(2 * n4w + 255) / 256, 256>>>((const float4*)W1,
                                                  (const float4*)W2);      // 3
    router_kernel<<<NTOK / 16, 256, SMEM_ROUTER>>>(x, noise, Wg, bg, Wn, bn); // 4

    moe_gemm_kernel<false><<<dim3(HDIM / BN, NEXP * 32), 256, SMEM_GEMM>>>(b1, nullptr);      // 5
    moe_gemm_kernel<true> <<<dim3(ODIM / BN, NEXP * 32), 256, SMEM_GEMM>>>(b2, (float*)d_out); // 6
}